// round 5
// baseline (speedup 1.0000x reference)
#include <cuda_runtime.h>
#include <cuda_bf16.h>
#include <cstdint>

#define N_NODES 50000
#define N_EDGES 800000
#define D 64
#define D2 128

#define SCAN_BLK 1024
#define NBLK_SCAN 49          // ceil(50000/1024)

#define WPB 6                 // warps per block in fused kernel
#define TPB (WPB * 32)        // 192 threads
#define GPW 8                 // nodes per warp per iteration

// dynamic smem layout for fused kernel
#define WP_FLOAT2 (D2 * 33)                     // 4224 float2 = 33792 B
#define HSH_OFF   (WP_FLOAT2 * 8)               // byte offset of hsh region
#define FUSED_SMEM (HSH_OFF + WPB * GPW * 32 * 16)   // + 24576 B = 58368 B

// ---------------------------------------------------------------------------
// Scratch (__device__ globals; no allocations anywhere)
// ---------------------------------------------------------------------------
struct __align__(8) EdgeRec { int s; float w; };

__device__ int     g_count[N_NODES];
__device__ int     g_start[N_NODES];
__device__ int     g_cursor[N_NODES];
__device__ int     g_bsum[NBLK_SCAN];
__device__ EdgeRec g_edge[N_EDGES];

// ---------------------------------------------------------------------------
// K1: zero degree counters
// ---------------------------------------------------------------------------
__global__ void zero_count_kernel() {
    int i = blockIdx.x * blockDim.x + threadIdx.x;
    if (i < N_NODES) g_count[i] = 0;
}

// ---------------------------------------------------------------------------
// K2: histogram dst -> in-degree (4 edges/thread)
// ---------------------------------------------------------------------------
__global__ void hist_kernel(const int* __restrict__ dst) {
    int t = blockIdx.x * blockDim.x + threadIdx.x;
    if (t >= N_EDGES / 4) return;
    int4 d4 = reinterpret_cast<const int4*>(dst)[t];
    atomicAdd(&g_count[d4.x], 1);
    atomicAdd(&g_count[d4.y], 1);
    atomicAdd(&g_count[d4.z], 1);
    atomicAdd(&g_count[d4.w], 1);
}

// ---------------------------------------------------------------------------
// K3a: per-block (1024-elem) exclusive scan, coalesced.
// ---------------------------------------------------------------------------
__global__ __launch_bounds__(SCAN_BLK) void scanA_kernel() {
    __shared__ int sh[SCAN_BLK];
    int t = threadIdx.x;
    int i = blockIdx.x * SCAN_BLK + t;
    int c = (i < N_NODES) ? g_count[i] : 0;
    sh[t] = c;
    __syncthreads();
    for (int d = 1; d < SCAN_BLK; d <<= 1) {
        int v = (t >= d) ? sh[t - d] : 0;
        __syncthreads();
        sh[t] += v;
        __syncthreads();
    }
    if (i < N_NODES) g_start[i] = sh[t] - c;   // exclusive within block
    if (t == SCAN_BLK - 1) g_bsum[blockIdx.x] = sh[t];
}

// ---------------------------------------------------------------------------
// K3b: add block offsets + init cursors. Block offset = sum of g_bsum[0..grp)
// computed by warp 0 in PARALLEL (2 loads/lane + shfl tree) instead of the
// serial MLP=1 loop that cost 6us in R4.
// ---------------------------------------------------------------------------
__global__ void scanC_kernel() {
    __shared__ int off_sh;
    int i = blockIdx.x * blockDim.x + threadIdx.x;
    int grp = (blockIdx.x * blockDim.x) >> 10;   // same for whole block
    if (threadIdx.x < 32) {
        int lane = threadIdx.x;
        int v = 0;
        if (lane < grp)      v += g_bsum[lane];
        if (lane + 32 < grp) v += g_bsum[lane + 32];
        #pragma unroll
        for (int o = 16; o > 0; o >>= 1) v += __shfl_down_sync(0xffffffffu, v, o);
        if (lane == 0) off_sh = v;
    }
    __syncthreads();
    if (i >= N_NODES) return;
    int v = g_start[i] + off_sh;
    g_start[i]  = v;
    g_cursor[i] = v;
}

// ---------------------------------------------------------------------------
// K4: position scatter — 4 edges/thread
// ---------------------------------------------------------------------------
__global__ void pos_kernel(const int* __restrict__ src,
                           const int* __restrict__ dst,
                           const float* __restrict__ w) {
    int t = blockIdx.x * blockDim.x + threadIdx.x;
    if (t >= N_EDGES / 4) return;
    int4   s4 = reinterpret_cast<const int4*>(src)[t];
    int4   d4 = reinterpret_cast<const int4*>(dst)[t];
    float4 w4 = reinterpret_cast<const float4*>(w)[t];

    int p0 = atomicAdd(&g_cursor[d4.x], 1);
    int p1 = atomicAdd(&g_cursor[d4.y], 1);
    int p2 = atomicAdd(&g_cursor[d4.z], 1);
    int p3 = atomicAdd(&g_cursor[d4.w], 1);

    EdgeRec r;
    r.s = s4.x; r.w = w4.x; g_edge[p0] = r;
    r.s = s4.y; r.w = w4.y; g_edge[p1] = r;
    r.s = s4.z; r.w = w4.z; g_edge[p2] = r;
    r.s = s4.w; r.w = w4.w; g_edge[p3] = r;
}

// ---------------------------------------------------------------------------
// K5: FUSED gather + normalize + concat + linear. GPW=8: W's LDS traffic
// amortized over 8 nodes -> matvec cleanly FFMA-bound (64 FFMA vs 16 LDS-wf
// per kq). Dynamic smem (58KB): Wp then hsh.
// ---------------------------------------------------------------------------
__global__ __launch_bounds__(TPB)
void fused_kernel(const float* __restrict__ h,
                  const float* __restrict__ W,   // [64, 128] row-major
                  const float* __restrict__ b,   // [64]
                  float* __restrict__ out) {     // [N, 64]
    extern __shared__ char smem[];
    float2* Wp = reinterpret_cast<float2*>(smem);                 // [D2*33]
    float4* hsh = reinterpret_cast<float4*>(smem + HSH_OFF);      // [WPB][GPW][32]

    int tid = threadIdx.x;
    for (int i = tid; i < D2 * 32; i += TPB) {
        int k = i >> 5;
        int o = i & 31;
        Wp[k * 33 + o] = make_float2(W[o * D2 + k], W[(o + 32) * D2 + k]);
    }
    __syncthreads();

    int warp = tid >> 5;
    int lane = tid & 31;
    float b0 = b[lane];
    float b1 = b[lane + 32];
    const float2* __restrict__ h2 = reinterpret_cast<const float2*>(h);
    float4* myh = hsh + (warp * GPW) * 32;       // this warp's GPW rows

    int gw = blockIdx.x * WPB + warp;
    int nwarps = gridDim.x * WPB;
    const int ngroups = (N_NODES + GPW - 1) / GPW;   // 6250

    for (int g = gw; g < ngroups; g += nwarps) {
        int n0 = g * GPW;

        // ---- phase A: gather ----
        #pragma unroll
        for (int u = 0; u < GPW; u++) {
            int n = n0 + u;
            if (n >= N_NODES) break;
            int beg = g_start[n];
            int cnt = g_count[n];
            float ax = 0.f, ay = 0.f;
            int j = 0;
            for (; j + 3 < cnt; j += 4) {
                EdgeRec e0 = g_edge[beg + j];
                EdgeRec e1 = g_edge[beg + j + 1];
                EdgeRec e2 = g_edge[beg + j + 2];
                EdgeRec e3 = g_edge[beg + j + 3];
                float2 h0 = h2[(size_t)e0.s * 32 + lane];
                float2 h1 = h2[(size_t)e1.s * 32 + lane];
                float2 hv2 = h2[(size_t)e2.s * 32 + lane];
                float2 h3 = h2[(size_t)e3.s * 32 + lane];
                ax += h0.x * e0.w + h1.x * e1.w + hv2.x * e2.w + h3.x * e3.w;
                ay += h0.y * e0.w + h1.y * e1.w + hv2.y * e2.w + h3.y * e3.w;
            }
            for (; j < cnt; j++) {
                EdgeRec e0 = g_edge[beg + j];
                float2 h0 = h2[(size_t)e0.s * 32 + lane];
                ax += h0.x * e0.w;
                ay += h0.y * e0.w;
            }
            float inv = 1.0f / fmaxf((float)cnt, 1.0f);
            float2* row2 = reinterpret_cast<float2*>(myh + u * 32);
            row2[lane]      = h2[(size_t)n * 32 + lane];          // h part
            row2[32 + lane] = make_float2(ax * inv, ay * inv);    // h_N part
        }
        __syncwarp();

        // ---- phase B: matvec ----
        float acc0[GPW], acc1[GPW];
        #pragma unroll
        for (int u = 0; u < GPW; u++) { acc0[u] = b0; acc1[u] = b1; }

        #pragma unroll 4
        for (int kq = 0; kq < D2 / 4; kq++) {
            float2 w0 = Wp[(4 * kq + 0) * 33 + lane];
            float2 w1 = Wp[(4 * kq + 1) * 33 + lane];
            float2 w2 = Wp[(4 * kq + 2) * 33 + lane];
            float2 w3 = Wp[(4 * kq + 3) * 33 + lane];
            #pragma unroll
            for (int u = 0; u < GPW; u++) {
                float4 hv = myh[u * 32 + kq];    // broadcast LDS.128
                acc0[u] += hv.x * w0.x + hv.y * w1.x + hv.z * w2.x + hv.w * w3.x;
                acc1[u] += hv.x * w0.y + hv.y * w1.y + hv.z * w2.y + hv.w * w3.y;
            }
        }

        #pragma unroll
        for (int u = 0; u < GPW; u++) {
            int n = n0 + u;
            if (n >= N_NODES) break;
            out[(size_t)n * D + lane]      = acc0[u];
            out[(size_t)n * D + lane + 32] = acc1[u];
        }
        __syncwarp();   // protect hsh before next iteration overwrites
    }
}

// ---------------------------------------------------------------------------
// Launch
// ---------------------------------------------------------------------------
extern "C" void kernel_launch(void* const* d_in, const int* in_sizes, int n_in,
                              void* d_out, int out_size) {
    const float* h   = (const float*)d_in[0];   // [50000, 64]
    const float* w   = (const float*)d_in[1];   // [800000]
    const int*   src = (const int*)  d_in[2];   // [800000]
    const int*   dst = (const int*)  d_in[3];   // [800000]
    const float* W   = (const float*)d_in[4];   // [64, 128]
    const float* b   = (const float*)d_in[5];   // [64]
    float* out = (float*)d_out;                 // [50000, 64]

    (void)in_sizes; (void)n_in; (void)out_size;

    // host-side attribute set (not an allocation; immediate, capture-safe)
    static bool attr_set = false;
    if (!attr_set) {
        cudaFuncSetAttribute(fused_kernel,
                             cudaFuncAttributeMaxDynamicSharedMemorySize,
                             FUSED_SMEM);
        attr_set = true;
    }

    zero_count_kernel<<<(N_NODES + 255) / 256, 256>>>();
    hist_kernel<<<(N_EDGES / 4 + 255) / 256, 256>>>(dst);
    scanA_kernel<<<NBLK_SCAN, SCAN_BLK>>>();
    scanC_kernel<<<(N_NODES + 255) / 256, 256>>>();
    pos_kernel<<<(N_EDGES / 4 + 255) / 256, 256>>>(src, dst, w);
    fused_kernel<<<592, TPB, FUSED_SMEM>>>(h, W, b, out);
}

// round 6
// speedup vs baseline: 1.2622x; 1.2622x over previous
#include <cuda_runtime.h>
#include <cuda_bf16.h>
#include <cstdint>

#define N_NODES 50000
#define N_EDGES 800000
#define D 64
#define D2 128

#define SCAN_BLK 1024
#define NBLK_SCAN 49          // ceil(50000/1024)

#define WPB 6                 // warps per block in fused kernel
#define TPB (WPB * 32)        // 192 threads
#define GPW 4                 // nodes per warp per iteration (R4 config)

// ---------------------------------------------------------------------------
// Scratch (__device__ globals; no allocations anywhere).
// INVARIANT: g_count is all-zero at kernel_launch entry. True initially
// (static zero-init) and re-established by fused_kernel at the end of each
// call (it zeroes each node's counter after consuming it).
// ---------------------------------------------------------------------------
struct __align__(8) EdgeRec { int s; float w; };

__device__ int     g_count[N_NODES];
__device__ int     g_start[N_NODES];
__device__ int     g_cursor[N_NODES];
__device__ int     g_total;
__device__ EdgeRec g_edge[N_EDGES];

// ---------------------------------------------------------------------------
// K1: histogram dst -> in-degree (4 edges/thread). Also resets g_total for
// the reserve kernel (stream order guarantees visibility).
// ---------------------------------------------------------------------------
__global__ void hist_kernel(const int* __restrict__ dst) {
    int t = blockIdx.x * blockDim.x + threadIdx.x;
    if (t == 0) g_total = 0;
    if (t >= N_EDGES / 4) return;
    int4 d4 = reinterpret_cast<const int4*>(dst)[t];
    atomicAdd(&g_count[d4.x], 1);
    atomicAdd(&g_count[d4.y], 1);
    atomicAdd(&g_count[d4.z], 1);
    atomicAdd(&g_count[d4.w], 1);
}

// ---------------------------------------------------------------------------
// K2: reserve CSR slices. Each block scans 1024 counts locally, claims a
// contiguous base via one atomicAdd on g_total, writes start/cursor.
// Slices are contiguous+disjoint; global order across blocks is irrelevant.
// Replaces scanA + scanC (one launch instead of two, no serial bsum chain).
// ---------------------------------------------------------------------------
__global__ __launch_bounds__(SCAN_BLK) void reserve_kernel() {
    __shared__ int sh[SCAN_BLK];
    __shared__ int base_sh;
    int t = threadIdx.x;
    int i = blockIdx.x * SCAN_BLK + t;
    int c = (i < N_NODES) ? g_count[i] : 0;
    sh[t] = c;
    __syncthreads();
    for (int d = 1; d < SCAN_BLK; d <<= 1) {
        int v = (t >= d) ? sh[t - d] : 0;
        __syncthreads();
        sh[t] += v;
        __syncthreads();
    }
    if (t == SCAN_BLK - 1) base_sh = atomicAdd(&g_total, sh[t]);
    __syncthreads();
    if (i < N_NODES) {
        int v = base_sh + sh[t] - c;   // exclusive local prefix + block base
        g_start[i]  = v;
        g_cursor[i] = v;
    }
}

// ---------------------------------------------------------------------------
// K3: position scatter — 4 edges/thread, 4 independent ATOMG in flight
// ---------------------------------------------------------------------------
__global__ void pos_kernel(const int* __restrict__ src,
                           const int* __restrict__ dst,
                           const float* __restrict__ w) {
    int t = blockIdx.x * blockDim.x + threadIdx.x;
    if (t >= N_EDGES / 4) return;
    int4   s4 = reinterpret_cast<const int4*>(src)[t];
    int4   d4 = reinterpret_cast<const int4*>(dst)[t];
    float4 w4 = reinterpret_cast<const float4*>(w)[t];

    int p0 = atomicAdd(&g_cursor[d4.x], 1);
    int p1 = atomicAdd(&g_cursor[d4.y], 1);
    int p2 = atomicAdd(&g_cursor[d4.z], 1);
    int p3 = atomicAdd(&g_cursor[d4.w], 1);

    EdgeRec r;
    r.s = s4.x; r.w = w4.x; g_edge[p0] = r;
    r.s = s4.y; r.w = w4.y; g_edge[p1] = r;
    r.s = s4.z; r.w = w4.z; g_edge[p2] = r;
    r.s = s4.w; r.w = w4.w; g_edge[p3] = r;
}

// ---------------------------------------------------------------------------
// K4: FUSED gather + normalize + concat + linear (exact R4 config:
// GPW=4, static 46KB smem, 4 CTAs/SM). Also re-zeroes g_count per node
// (maintains the entry invariant; replaces the zero kernel).
// ---------------------------------------------------------------------------
__global__ __launch_bounds__(TPB)
void fused_kernel(const float* __restrict__ h,
                  const float* __restrict__ W,   // [64, 128] row-major
                  const float* __restrict__ b,   // [64]
                  float* __restrict__ out) {     // [N, 64]
    __shared__ float2 Wp[D2 * 33];               // Wp[k*33+o], o in 0..31
    __shared__ float4 hsh4[WPB][GPW][D2 / 4];    // concat rows, float4 view

    int tid = threadIdx.x;
    for (int i = tid; i < D2 * 32; i += TPB) {
        int k = i >> 5;
        int o = i & 31;
        Wp[k * 33 + o] = make_float2(W[o * D2 + k], W[(o + 32) * D2 + k]);
    }
    __syncthreads();

    int warp = tid >> 5;
    int lane = tid & 31;
    float b0 = b[lane];
    float b1 = b[lane + 32];
    const float2* __restrict__ h2 = reinterpret_cast<const float2*>(h);

    int gw = blockIdx.x * WPB + warp;
    int nwarps = gridDim.x * WPB;
    const int ngroups = (N_NODES + GPW - 1) / GPW;   // 12500

    for (int g = gw; g < ngroups; g += nwarps) {
        int n0 = g * GPW;

        // ---- phase A: gather ----
        #pragma unroll
        for (int u = 0; u < GPW; u++) {
            int n = n0 + u;
            if (n >= N_NODES) break;
            int beg = g_start[n];
            int cnt = g_count[n];
            float ax = 0.f, ay = 0.f;
            int j = 0;
            for (; j + 3 < cnt; j += 4) {
                EdgeRec e0 = g_edge[beg + j];
                EdgeRec e1 = g_edge[beg + j + 1];
                EdgeRec e2 = g_edge[beg + j + 2];
                EdgeRec e3 = g_edge[beg + j + 3];
                float2 h0 = h2[(size_t)e0.s * 32 + lane];
                float2 h1 = h2[(size_t)e1.s * 32 + lane];
                float2 hv2 = h2[(size_t)e2.s * 32 + lane];
                float2 h3 = h2[(size_t)e3.s * 32 + lane];
                ax += h0.x * e0.w + h1.x * e1.w + hv2.x * e2.w + h3.x * e3.w;
                ay += h0.y * e0.w + h1.y * e1.w + hv2.y * e2.w + h3.y * e3.w;
            }
            for (; j < cnt; j++) {
                EdgeRec e0 = g_edge[beg + j];
                float2 h0 = h2[(size_t)e0.s * 32 + lane];
                ax += h0.x * e0.w;
                ay += h0.y * e0.w;
            }
            // maintain the all-zero invariant for the next call
            if (lane == 0) g_count[n] = 0;
            float inv = 1.0f / fmaxf((float)cnt, 1.0f);
            float2* row2 = reinterpret_cast<float2*>(&hsh4[warp][u][0]);
            row2[lane]      = h2[(size_t)n * 32 + lane];          // h part
            row2[32 + lane] = make_float2(ax * inv, ay * inv);    // h_N part
        }
        __syncwarp();

        // ---- phase B: matvec ----
        float acc0[GPW], acc1[GPW];
        #pragma unroll
        for (int u = 0; u < GPW; u++) { acc0[u] = b0; acc1[u] = b1; }

        #pragma unroll 4
        for (int kq = 0; kq < D2 / 4; kq++) {
            float2 w0 = Wp[(4 * kq + 0) * 33 + lane];
            float2 w1 = Wp[(4 * kq + 1) * 33 + lane];
            float2 w2 = Wp[(4 * kq + 2) * 33 + lane];
            float2 w3 = Wp[(4 * kq + 3) * 33 + lane];
            #pragma unroll
            for (int u = 0; u < GPW; u++) {
                float4 hv = hsh4[warp][u][kq];   // broadcast LDS.128
                acc0[u] += hv.x * w0.x + hv.y * w1.x + hv.z * w2.x + hv.w * w3.x;
                acc1[u] += hv.x * w0.y + hv.y * w1.y + hv.z * w2.y + hv.w * w3.y;
            }
        }

        #pragma unroll
        for (int u = 0; u < GPW; u++) {
            int n = n0 + u;
            if (n >= N_NODES) break;
            out[(size_t)n * D + lane]      = acc0[u];
            out[(size_t)n * D + lane + 32] = acc1[u];
        }
        __syncwarp();   // protect hsh before next iteration overwrites
    }
}

// ---------------------------------------------------------------------------
// Launch — 4 kernels (was 6)
// ---------------------------------------------------------------------------
extern "C" void kernel_launch(void* const* d_in, const int* in_sizes, int n_in,
                              void* d_out, int out_size) {
    const float* h   = (const float*)d_in[0];   // [50000, 64]
    const float* w   = (const float*)d_in[1];   // [800000]
    const int*   src = (const int*)  d_in[2];   // [800000]
    const int*   dst = (const int*)  d_in[3];   // [800000]
    const float* W   = (const float*)d_in[4];   // [64, 128]
    const float* b   = (const float*)d_in[5];   // [64]
    float* out = (float*)d_out;                 // [50000, 64]

    (void)in_sizes; (void)n_in; (void)out_size;

    hist_kernel<<<(N_EDGES / 4 + 255) / 256, 256>>>(dst);
    reserve_kernel<<<NBLK_SCAN, SCAN_BLK>>>();
    pos_kernel<<<(N_EDGES / 4 + 255) / 256, 256>>>(src, dst, w);
    fused_kernel<<<592, TPB>>>(h, W, b, out);
}